// round 1
// baseline (speedup 1.0000x reference)
#include <cuda_runtime.h>
#include <math.h>
#include <stdint.h>

#define B_ 32
#define T_ 1024
#define D_ 512
#define H_ 2048
#define E_ 8

#define BM 128
#define BN 128
#define BK 16
#define PADM 4
#define PADN 4

// Routing scratch + h scratch (both slots concatenated along K: [B][T][2*H])
__device__ int   g_eidx[B_][2];
__device__ float g_prob[B_][2];
__device__ float g_h[(size_t)B_ * T_ * (2 * H_)];   // 512 MB

// ---------------------------------------------------------------------------
// helpers
// ---------------------------------------------------------------------------
__device__ __forceinline__ unsigned f2tf32(float f) {
    unsigned u;
    asm("cvt.rna.tf32.f32 %0, %1;" : "=r"(u) : "f"(f));
    return u;
}

__device__ __forceinline__ void mma_tf32(float* d, const unsigned* a, const unsigned* b) {
    asm volatile(
        "mma.sync.aligned.m16n8k8.row.col.f32.tf32.tf32.f32 "
        "{%0,%1,%2,%3}, {%4,%5,%6,%7}, {%8,%9}, {%0,%1,%2,%3};\n"
        : "+f"(d[0]), "+f"(d[1]), "+f"(d[2]), "+f"(d[3])
        : "r"(a[0]), "r"(a[1]), "r"(a[2]), "r"(a[3]), "r"(b[0]), "r"(b[1]));
}

// ---------------------------------------------------------------------------
// Kernel 1: gating (pooled mean -> logits -> top2 -> softmax)
// ---------------------------------------------------------------------------
__global__ void gate_kernel(const float* __restrict__ x,
                            const float* __restrict__ gw,
                            const float* __restrict__ gb,
                            float* __restrict__ out_logits) {
    __shared__ float pooled[D_];
    __shared__ float logits[E_];
    const int b = blockIdx.x;
    const int d = threadIdx.x;                 // 512 threads
    const float* xb = x + (size_t)b * T_ * D_;
    float s = 0.f;
    for (int t = 0; t < T_; t++) s += xb[(size_t)t * D_ + d];
    pooled[d] = s * (1.0f / (float)T_);
    __syncthreads();

    const int w = threadIdx.x >> 5, lane = threadIdx.x & 31;
    if (w < E_) {
        float acc = 0.f;
        for (int j = lane; j < D_; j += 32) acc += pooled[j] * gw[(size_t)j * E_ + w];
        #pragma unroll
        for (int o = 16; o > 0; o >>= 1) acc += __shfl_xor_sync(0xffffffffu, acc, o);
        if (lane == 0) logits[w] = acc + gb[w];
    }
    __syncthreads();

    if (threadIdx.x == 0) {
        int   i0 = 0;     float l0 = logits[0];
        for (int e = 1; e < E_; e++) if (logits[e] > l0) { l0 = logits[e]; i0 = e; }
        int   i1 = -1;    float l1 = -1e30f;
        for (int e = 0; e < E_; e++) if (e != i0 && logits[e] > l1) { l1 = logits[e]; i1 = e; }
        float e0 = 1.0f;                   // exp(l0 - l0)
        float e1 = expf(l1 - l0);
        float inv = 1.0f / (e0 + e1);
        g_eidx[b][0] = i0; g_eidx[b][1] = i1;
        g_prob[b][0] = e0 * inv; g_prob[b][1] = e1 * inv;
        for (int e = 0; e < E_; e++) out_logits[b * E_ + e] = logits[e];
    }
}

// ---------------------------------------------------------------------------
// Kernel 2: h[b][t][slot*H + n] = p * silu( x[b] @ w1[e]  + b1[e] )
// A: x[b]   [T, D]  row-major (lda = D)
// B: w1[e]  [D, H]  row-major (ldb = H)
// ---------------------------------------------------------------------------
__global__ __launch_bounds__(256, 2) void gemm1_kernel(const float* __restrict__ x,
                                                       const float* __restrict__ w1,
                                                       const float* __restrict__ b1) {
    __shared__ __align__(16) unsigned As[2][BK][BM + PADM];  // col-major: As[k][m]
    __shared__ __align__(16) unsigned Bs[2][BK][BN + PADN];  // Bs[k][n]

    const int bz = blockIdx.z;
    const int b = bz >> 1, slot = bz & 1;
    const int e = g_eidx[b][slot];
    const float p = g_prob[b][slot];
    const float* Ag = x  + (size_t)b * T_ * D_;
    const float* Bg = w1 + (size_t)e * D_ * H_;

    const int m0 = blockIdx.y * BM;
    const int n0 = blockIdx.x * BN;
    const int tid  = threadIdx.x;
    const int warp = tid >> 5;
    const int lane = tid & 31;
    const int g  = lane >> 2;     // groupID
    const int t4 = lane & 3;      // threadID_in_group
    const int wm = (warp & 1) * 64;
    const int wn = (warp >> 1) * 32;

    float acc[4][4][4];
    #pragma unroll
    for (int i = 0; i < 4; i++)
        #pragma unroll
        for (int j = 0; j < 4; j++)
            #pragma unroll
            for (int r = 0; r < 4; r++) acc[i][j][r] = 0.f;

    // per-thread load assignments (2 float4 chunks for A, 2 for B)
    const int ca0 = tid, ca1 = tid + 256;        // A: r = c>>2, kc = (c&3)*4
    const int ra0 = ca0 >> 2, ka0 = (ca0 & 3) * 4;
    const int ra1 = ca1 >> 2, ka1 = (ca1 & 3) * 4;
    const int rb0 = ca0 >> 5, nb0 = (ca0 & 31) * 4;  // B: r = c>>5, nc = (c&31)*4
    const int rb1 = ca1 >> 5, nb1 = (ca1 & 31) * 4;

    float4 ta0, ta1, tb0, tb1;

    // prologue: LDG kt=0 + STS buf 0
    {
        ta0 = *(const float4*)(Ag + (size_t)(m0 + ra0) * D_ + ka0);
        ta1 = *(const float4*)(Ag + (size_t)(m0 + ra1) * D_ + ka1);
        tb0 = *(const float4*)(Bg + (size_t)(rb0) * H_ + n0 + nb0);
        tb1 = *(const float4*)(Bg + (size_t)(rb1) * H_ + n0 + nb1);
        As[0][ka0+0][ra0] = f2tf32(ta0.x); As[0][ka0+1][ra0] = f2tf32(ta0.y);
        As[0][ka0+2][ra0] = f2tf32(ta0.z); As[0][ka0+3][ra0] = f2tf32(ta0.w);
        As[0][ka1+0][ra1] = f2tf32(ta1.x); As[0][ka1+1][ra1] = f2tf32(ta1.y);
        As[0][ka1+2][ra1] = f2tf32(ta1.z); As[0][ka1+3][ra1] = f2tf32(ta1.w);
        uint4 v0 = make_uint4(f2tf32(tb0.x), f2tf32(tb0.y), f2tf32(tb0.z), f2tf32(tb0.w));
        uint4 v1 = make_uint4(f2tf32(tb1.x), f2tf32(tb1.y), f2tf32(tb1.z), f2tf32(tb1.w));
        *(uint4*)&Bs[0][rb0][nb0] = v0;
        *(uint4*)&Bs[0][rb1][nb1] = v1;
    }
    __syncthreads();

    const int NK = D_ / BK;   // 32
    for (int kt = 0; kt < NK; ++kt) {
        const int buf = kt & 1;
        const bool pf = (kt + 1 < NK);
        if (pf) {
            const int k0 = (kt + 1) * BK;
            ta0 = *(const float4*)(Ag + (size_t)(m0 + ra0) * D_ + k0 + ka0);
            ta1 = *(const float4*)(Ag + (size_t)(m0 + ra1) * D_ + k0 + ka1);
            tb0 = *(const float4*)(Bg + (size_t)(k0 + rb0) * H_ + n0 + nb0);
            tb1 = *(const float4*)(Bg + (size_t)(k0 + rb1) * H_ + n0 + nb1);
        }
        #pragma unroll
        for (int ks = 0; ks < 2; ks++) {
            const int k = ks * 8;
            unsigned af[4][4], bf[4][2];
            #pragma unroll
            for (int mt = 0; mt < 4; mt++) {
                const int m = wm + mt * 16;
                af[mt][0] = As[buf][k + t4    ][m + g    ];
                af[mt][1] = As[buf][k + t4    ][m + g + 8];
                af[mt][2] = As[buf][k + t4 + 4][m + g    ];
                af[mt][3] = As[buf][k + t4 + 4][m + g + 8];
            }
            #pragma unroll
            for (int nt = 0; nt < 4; nt++) {
                const int n = wn + nt * 8 + g;
                bf[nt][0] = Bs[buf][k + t4    ][n];
                bf[nt][1] = Bs[buf][k + t4 + 4][n];
            }
            #pragma unroll
            for (int mt = 0; mt < 4; mt++)
                #pragma unroll
                for (int nt = 0; nt < 4; nt++)
                    mma_tf32(acc[mt][nt], af[mt], bf[nt]);
        }
        if (pf) {
            const int nb = buf ^ 1;
            As[nb][ka0+0][ra0] = f2tf32(ta0.x); As[nb][ka0+1][ra0] = f2tf32(ta0.y);
            As[nb][ka0+2][ra0] = f2tf32(ta0.z); As[nb][ka0+3][ra0] = f2tf32(ta0.w);
            As[nb][ka1+0][ra1] = f2tf32(ta1.x); As[nb][ka1+1][ra1] = f2tf32(ta1.y);
            As[nb][ka1+2][ra1] = f2tf32(ta1.z); As[nb][ka1+3][ra1] = f2tf32(ta1.w);
            uint4 v0 = make_uint4(f2tf32(tb0.x), f2tf32(tb0.y), f2tf32(tb0.z), f2tf32(tb0.w));
            uint4 v1 = make_uint4(f2tf32(tb1.x), f2tf32(tb1.y), f2tf32(tb1.z), f2tf32(tb1.w));
            *(uint4*)&Bs[nb][rb0][nb0] = v0;
            *(uint4*)&Bs[nb][rb1][nb1] = v1;
        }
        __syncthreads();
    }

    // epilogue: +b1, silu, *p, write to scratch
    float* Hout = g_h + (size_t)b * T_ * (2 * H_) + (size_t)slot * H_;
    #pragma unroll
    for (int mt = 0; mt < 4; mt++) {
        #pragma unroll
        for (int nt = 0; nt < 4; nt++) {
            #pragma unroll
            for (int half = 0; half < 2; half++) {
                const int row = m0 + wm + mt * 16 + g + half * 8;
                const int col = n0 + wn + nt * 8 + t4 * 2;
                float v0 = acc[mt][nt][half * 2 + 0] + b1[e * H_ + col];
                float v1 = acc[mt][nt][half * 2 + 1] + b1[e * H_ + col + 1];
                v0 = p * v0 * (1.0f / (1.0f + __expf(-v0)));
                v1 = p * v1 * (1.0f / (1.0f + __expf(-v1)));
                *(float2*)&Hout[(size_t)row * (2 * H_) + col] = make_float2(v0, v1);
            }
        }
    }
}

// ---------------------------------------------------------------------------
// Kernel 3: out[b] = h_cat[b] @ [w2[e0]; w2[e1]]  + p0*b2[e0] + p1*b2[e1] + x[b]
// A: g_h[b]  [T, 2H] row-major (lda = 4096)
// B: row kk -> w2[e_(kk>=H)] row (kk mod H), [*, D] row-major (ldb = D)
// ---------------------------------------------------------------------------
__global__ __launch_bounds__(256, 2) void gemm2_kernel(const float* __restrict__ x,
                                                       const float* __restrict__ w2,
                                                       const float* __restrict__ b2,
                                                       float* __restrict__ out) {
    __shared__ __align__(16) unsigned As[2][BK][BM + PADM];
    __shared__ __align__(16) unsigned Bs[2][BK][BN + PADN];

    const int b = blockIdx.z;
    const int e0 = g_eidx[b][0], e1 = g_eidx[b][1];
    const float p0 = g_prob[b][0], p1 = g_prob[b][1];
    const float* Ag = g_h + (size_t)b * T_ * (2 * H_);
    const int LDA = 2 * H_;   // 4096

    const int m0 = blockIdx.y * BM;
    const int n0 = blockIdx.x * BN;
    const int tid  = threadIdx.x;
    const int warp = tid >> 5;
    const int lane = tid & 31;
    const int g  = lane >> 2;
    const int t4 = lane & 3;
    const int wm = (warp & 1) * 64;
    const int wn = (warp >> 1) * 32;

    float acc[4][4][4];
    #pragma unroll
    for (int i = 0; i < 4; i++)
        #pragma unroll
        for (int j = 0; j < 4; j++)
            #pragma unroll
            for (int r = 0; r < 4; r++) acc[i][j][r] = 0.f;

    const int ca0 = tid, ca1 = tid + 256;
    const int ra0 = ca0 >> 2, ka0 = (ca0 & 3) * 4;
    const int ra1 = ca1 >> 2, ka1 = (ca1 & 3) * 4;
    const int rb0 = ca0 >> 5, nb0 = (ca0 & 31) * 4;
    const int rb1 = ca1 >> 5, nb1 = (ca1 & 31) * 4;

    float4 ta0, ta1, tb0, tb1;

    // B row pointer for concatenated-K weight
    #define BROW(kk) (w2 + (size_t)(((kk) < H_) ? e0 : e1) * H_ * D_ + (size_t)((kk) & (H_ - 1)) * D_)

    {
        ta0 = *(const float4*)(Ag + (size_t)(m0 + ra0) * LDA + ka0);
        ta1 = *(const float4*)(Ag + (size_t)(m0 + ra1) * LDA + ka1);
        tb0 = *(const float4*)(BROW(rb0) + n0 + nb0);
        tb1 = *(const float4*)(BROW(rb1) + n0 + nb1);
        As[0][ka0+0][ra0] = f2tf32(ta0.x); As[0][ka0+1][ra0] = f2tf32(ta0.y);
        As[0][ka0+2][ra0] = f2tf32(ta0.z); As[0][ka0+3][ra0] = f2tf32(ta0.w);
        As[0][ka1+0][ra1] = f2tf32(ta1.x); As[0][ka1+1][ra1] = f2tf32(ta1.y);
        As[0][ka1+2][ra1] = f2tf32(ta1.z); As[0][ka1+3][ra1] = f2tf32(ta1.w);
        uint4 v0 = make_uint4(f2tf32(tb0.x), f2tf32(tb0.y), f2tf32(tb0.z), f2tf32(tb0.w));
        uint4 v1 = make_uint4(f2tf32(tb1.x), f2tf32(tb1.y), f2tf32(tb1.z), f2tf32(tb1.w));
        *(uint4*)&Bs[0][rb0][nb0] = v0;
        *(uint4*)&Bs[0][rb1][nb1] = v1;
    }
    __syncthreads();

    const int NK = (2 * H_) / BK;   // 256
    for (int kt = 0; kt < NK; ++kt) {
        const int buf = kt & 1;
        const bool pf = (kt + 1 < NK);
        if (pf) {
            const int k0 = (kt + 1) * BK;
            ta0 = *(const float4*)(Ag + (size_t)(m0 + ra0) * LDA + k0 + ka0);
            ta1 = *(const float4*)(Ag + (size_t)(m0 + ra1) * LDA + k0 + ka1);
            tb0 = *(const float4*)(BROW(k0 + rb0) + n0 + nb0);
            tb1 = *(const float4*)(BROW(k0 + rb1) + n0 + nb1);
        }
        #pragma unroll
        for (int ks = 0; ks < 2; ks++) {
            const int k = ks * 8;
            unsigned af[4][4], bf[4][2];
            #pragma unroll
            for (int mt = 0; mt < 4; mt++) {
                const int m = wm + mt * 16;
                af[mt][0] = As[buf][k + t4    ][m + g    ];
                af[mt][1] = As[buf][k + t4    ][m + g + 8];
                af[mt][2] = As[buf][k + t4 + 4][m + g    ];
                af[mt][3] = As[buf][k + t4 + 4][m + g + 8];
            }
            #pragma unroll
            for (int nt = 0; nt < 4; nt++) {
                const int n = wn + nt * 8 + g;
                bf[nt][0] = Bs[buf][k + t4    ][n];
                bf[nt][1] = Bs[buf][k + t4 + 4][n];
            }
            #pragma unroll
            for (int mt = 0; mt < 4; mt++)
                #pragma unroll
                for (int nt = 0; nt < 4; nt++)
                    mma_tf32(acc[mt][nt], af[mt], bf[nt]);
        }
        if (pf) {
            const int nb = buf ^ 1;
            As[nb][ka0+0][ra0] = f2tf32(ta0.x); As[nb][ka0+1][ra0] = f2tf32(ta0.y);
            As[nb][ka0+2][ra0] = f2tf32(ta0.z); As[nb][ka0+3][ra0] = f2tf32(ta0.w);
            As[nb][ka1+0][ra1] = f2tf32(ta1.x); As[nb][ka1+1][ra1] = f2tf32(ta1.y);
            As[nb][ka1+2][ra1] = f2tf32(ta1.z); As[nb][ka1+3][ra1] = f2tf32(ta1.w);
            uint4 v0 = make_uint4(f2tf32(tb0.x), f2tf32(tb0.y), f2tf32(tb0.z), f2tf32(tb0.w));
            uint4 v1 = make_uint4(f2tf32(tb1.x), f2tf32(tb1.y), f2tf32(tb1.z), f2tf32(tb1.w));
            *(uint4*)&Bs[nb][rb0][nb0] = v0;
            *(uint4*)&Bs[nb][rb1][nb1] = v1;
        }
        __syncthreads();
    }
    #undef BROW

    // epilogue: + p0*b2[e0] + p1*b2[e1] + x, write out
    const float* xb = x + (size_t)b * T_ * D_;
    float* ob = out + (size_t)b * T_ * D_;
    #pragma unroll
    for (int mt = 0; mt < 4; mt++) {
        #pragma unroll
        for (int nt = 0; nt < 4; nt++) {
            #pragma unroll
            for (int half = 0; half < 2; half++) {
                const int row = m0 + wm + mt * 16 + g + half * 8;
                const int col = n0 + wn + nt * 8 + t4 * 2;
                const float bias0 = p0 * b2[e0 * D_ + col]     + p1 * b2[e1 * D_ + col];
                const float bias1 = p0 * b2[e0 * D_ + col + 1] + p1 * b2[e1 * D_ + col + 1];
                const float2 xv = *(const float2*)&xb[(size_t)row * D_ + col];
                float v0 = acc[mt][nt][half * 2 + 0] + bias0 + xv.x;
                float v1 = acc[mt][nt][half * 2 + 1] + bias1 + xv.y;
                *(float2*)&ob[(size_t)row * D_ + col] = make_float2(v0, v1);
            }
        }
    }
}

// ---------------------------------------------------------------------------
extern "C" void kernel_launch(void* const* d_in, const int* in_sizes, int n_in,
                              void* d_out, int out_size) {
    const float* x  = (const float*)d_in[0];
    const float* gw = (const float*)d_in[1];
    const float* gb = (const float*)d_in[2];
    const float* w1 = (const float*)d_in[3];
    const float* b1 = (const float*)d_in[4];
    const float* w2 = (const float*)d_in[5];
    const float* b2 = (const float*)d_in[6];

    float* out = (float*)d_out;
    float* out_logits = out + (size_t)B_ * T_ * D_;

    gate_kernel<<<B_, D_>>>(x, gw, gb, out_logits);

    dim3 g1(H_ / BN, T_ / BM, B_ * 2);   // (16, 8, 64)
    gemm1_kernel<<<g1, 256>>>(x, w1, b1);

    dim3 g2(D_ / BN, T_ / BM, B_);       // (4, 8, 32)
    gemm2_kernel<<<g2, 256>>>(x, w2, b2, out);
}

// round 3
// speedup vs baseline: 1.5200x; 1.5200x over previous
#include <cuda_runtime.h>
#include <math.h>
#include <stdint.h>

#define B_ 32
#define T_ 1024
#define D_ 512
#define H_ 2048
#define E_ 8

#define BM 128
#define BN 128
#define BK 32
#define STAGES 3

#define ASTR 36            // floats per A row (padded)
#define BSTR 136           // floats per B row (padded)
#define A_BYTES (BM * ASTR * 4)        // 18432
#define B_BYTES (BK * BSTR * 4)        // 17408
#define STAGE_BYTES (A_BYTES + B_BYTES) // 35840
#define SMEMSZ (STAGES * STAGE_BYTES)   // 107520

// ---------------------------------------------------------------------------
// scratch (device globals — no allocation allowed)
// ---------------------------------------------------------------------------
__device__ int   g_eidx[B_][2];
__device__ float g_prob[B_][2];
__device__ float g_pool[B_][8][D_];
__device__ float g_xc[(size_t)B_ * T_ * D_];        // tf32-RNA x
__device__ float g_w1c[(size_t)E_ * D_ * H_];       // tf32-RNA w1 (same layout)
__device__ float g_w2c[(size_t)E_ * H_ * D_];       // tf32-RNA w2
__device__ float g_h[(size_t)B_ * T_ * (2 * H_)];   // p*silu(...), tf32-RNA

// ---------------------------------------------------------------------------
// helpers
// ---------------------------------------------------------------------------
__device__ __forceinline__ unsigned f2tf32(float f) {
    unsigned u;
    asm("cvt.rna.tf32.f32 %0, %1;" : "=r"(u) : "f"(f));
    return u;
}
__device__ __forceinline__ float rna32(float f) { return __uint_as_float(f2tf32(f)); }

__device__ __forceinline__ uint32_t smem_u32(const void* p) {
    uint32_t a;
    asm("{ .reg .u64 t; cvta.to.shared.u64 t, %1; cvt.u32.u64 %0, t; }" : "=r"(a) : "l"(p));
    return a;
}
__device__ __forceinline__ void cp16(uint32_t dst, const void* src) {
    asm volatile("cp.async.cg.shared.global [%0], [%1], 16;" :: "r"(dst), "l"(src));
}
__device__ __forceinline__ void cp_commit() {
    asm volatile("cp.async.commit_group;" ::: "memory");
}
template <int N>
__device__ __forceinline__ void cp_wait() {
    asm volatile("cp.async.wait_group %0;" :: "n"(N) : "memory");
}

__device__ __forceinline__ void mma_tf32(float* d, const unsigned* a, const unsigned* b) {
    asm volatile(
        "mma.sync.aligned.m16n8k8.row.col.f32.tf32.tf32.f32 "
        "{%0,%1,%2,%3}, {%4,%5,%6,%7}, {%8,%9}, {%0,%1,%2,%3};\n"
        : "+f"(d[0]), "+f"(d[1]), "+f"(d[2]), "+f"(d[3])
        : "r"(a[0]), "r"(a[1]), "r"(a[2]), "r"(a[3]), "r"(b[0]), "r"(b[1]));
}

// ---------------------------------------------------------------------------
// prep kernels
// ---------------------------------------------------------------------------
// pooling partials + tf32-rounded copy of x
__global__ void pool_convert_kernel(const float* __restrict__ x) {
    const int b = blockIdx.x, ch = blockIdx.y, d = threadIdx.x;   // 512 threads
    const size_t base = ((size_t)b * T_ + (size_t)ch * 128) * D_ + d;
    float s = 0.f;
    for (int t = 0; t < 128; t++) {
        float v = x[base + (size_t)t * D_];
        s += v;
        g_xc[base + (size_t)t * D_] = rna32(v);
    }
    g_pool[b][ch][d] = s;
}

// elementwise tf32-RNA rounding copy (float4 grid-stride)
__global__ void round_copy_kernel(const float* __restrict__ src, float* __restrict__ dst,
                                  size_t n4) {
    const size_t i = (size_t)blockIdx.x * blockDim.x + threadIdx.x;
    if (i < n4) {
        float4 v = ((const float4*)src)[i];
        v.x = rna32(v.x); v.y = rna32(v.y); v.z = rna32(v.z); v.w = rna32(v.w);
        ((float4*)dst)[i] = v;
    }
}

// finish gating: logits, top-2, softmax
__global__ void gate_kernel(const float* __restrict__ gw, const float* __restrict__ gb,
                            float* __restrict__ out_logits) {
    __shared__ float pooled[D_];
    __shared__ float logits[E_];
    const int b = blockIdx.x, d = threadIdx.x;
    float s = 0.f;
    #pragma unroll
    for (int c = 0; c < 8; c++) s += g_pool[b][c][d];
    pooled[d] = s * (1.0f / (float)T_);
    __syncthreads();
    const int w = threadIdx.x >> 5, lane = threadIdx.x & 31;
    if (w < E_) {
        float acc = 0.f;
        for (int j = lane; j < D_; j += 32) acc += pooled[j] * gw[(size_t)j * E_ + w];
        #pragma unroll
        for (int o = 16; o > 0; o >>= 1) acc += __shfl_xor_sync(0xffffffffu, acc, o);
        if (lane == 0) logits[w] = acc + gb[w];
    }
    __syncthreads();
    if (threadIdx.x == 0) {
        int i0 = 0; float l0 = logits[0];
        for (int e = 1; e < E_; e++) if (logits[e] > l0) { l0 = logits[e]; i0 = e; }
        int i1 = -1; float l1 = -1e30f;
        for (int e = 0; e < E_; e++) if (e != i0 && logits[e] > l1) { l1 = logits[e]; i1 = e; }
        float e1 = expf(l1 - l0);
        float inv = 1.0f / (1.0f + e1);
        g_eidx[b][0] = i0; g_eidx[b][1] = i1;
        g_prob[b][0] = inv; g_prob[b][1] = e1 * inv;
        for (int e = 0; e < E_; e++) out_logits[b * E_ + e] = logits[e];
    }
}

// ---------------------------------------------------------------------------
// GEMM core macros (shared by both GEMM kernels)
// 256 threads, 8 warps in 2(m)x4(n) layout; warp tile 64x32; BK=32 (4 k8 steps)
// A smem: [BM][ASTR] row-major; B smem: [BK][BSTR] (k rows, n contiguous)
// ---------------------------------------------------------------------------

// issue cp.async for one stage; A_SRC(row, c16) / B_SRC(row, c16) give global ptrs
#define ISSUE_STAGE(slot, A_SRC, B_SRC) do {                                   \
    const uint32_t _as = sm_base + (slot) * STAGE_BYTES;                       \
    const uint32_t _bs = _as + A_BYTES;                                        \
    _Pragma("unroll")                                                          \
    for (int _i = 0; _i < 4; _i++) {                                           \
        const int _ca = _i * 256 + tid;                                        \
        const int _ra = _ca >> 3, _cc = _ca & 7;                               \
        cp16(_as + _ra * (ASTR * 4) + _cc * 16, (A_SRC(_ra, _cc)));            \
    }                                                                          \
    _Pragma("unroll")                                                          \
    for (int _i = 0; _i < 4; _i++) {                                           \
        const int _cb = _i * 256 + tid;                                        \
        const int _rb = _cb >> 5, _cc = _cb & 31;                              \
        cp16(_bs + _rb * (BSTR * 4) + _cc * 16, (B_SRC(_rb, _cc)));            \
    }                                                                          \
} while (0)

#define COMPUTE_STAGE(slot) do {                                               \
    const float* _A = (const float*)(smem + (slot) * STAGE_BYTES);             \
    const float* _Bt = (const float*)(smem + (slot) * STAGE_BYTES + A_BYTES);  \
    _Pragma("unroll")                                                          \
    for (int ks = 0; ks < 4; ks++) {                                           \
        const int k = ks * 8;                                                  \
        unsigned af[4][4], bf[4][2];                                           \
        _Pragma("unroll")                                                      \
        for (int mt = 0; mt < 4; mt++) {                                       \
            const int m = wm + mt * 16;                                        \
            af[mt][0] = __float_as_uint(_A[(m + g    ) * ASTR + k + t4    ]);  \
            af[mt][1] = __float_as_uint(_A[(m + g + 8) * ASTR + k + t4    ]);  \
            af[mt][2] = __float_as_uint(_A[(m + g    ) * ASTR + k + t4 + 4]);  \
            af[mt][3] = __float_as_uint(_A[(m + g + 8) * ASTR + k + t4 + 4]);  \
        }                                                                      \
        _Pragma("unroll")                                                      \
        for (int nt = 0; nt < 4; nt++) {                                       \
            const int n = wn + nt * 8 + g;                                     \
            bf[nt][0] = __float_as_uint(_Bt[(k + t4    ) * BSTR + n]);         \
            bf[nt][1] = __float_as_uint(_Bt[(k + t4 + 4) * BSTR + n]);         \
        }                                                                      \
        _Pragma("unroll")                                                      \
        for (int mt = 0; mt < 4; mt++)                                         \
            _Pragma("unroll")                                                  \
            for (int nt = 0; nt < 4; nt++)                                     \
                mma_tf32(acc[mt][nt], af[mt], bf[nt]);                         \
    }                                                                          \
} while (0)

// ---------------------------------------------------------------------------
// GEMM1: h[b][t][slot*H + n] = rna( p * silu( xc[b] @ w1c[e] + b1[e] ) )
// A: g_xc[b]  [T, D] row-major; B: g_w1c[e] [D, H] row-major (k rows)
// grid (H/BN=16, T/BM=8, B*2=64)
// ---------------------------------------------------------------------------
__global__ __launch_bounds__(256, 2) void gemm1_kernel(const float* __restrict__ b1) {
    extern __shared__ char smem[];
    const uint32_t sm_base = smem_u32(smem);

    const int bz = blockIdx.z, b = bz >> 1, slot = bz & 1;
    const int e = g_eidx[b][slot];
    const float p = g_prob[b][slot];
    const int m0 = blockIdx.y * BM;
    const int n0 = blockIdx.x * BN;
    const int tid  = threadIdx.x;
    const int warp = tid >> 5, lane = tid & 31;
    const int g = lane >> 2, t4 = lane & 3;
    const int wm = (warp & 1) * 64;
    const int wn = (warp >> 1) * 32;

    const float* Ag = g_xc  + ((size_t)b * T_ + m0) * D_;
    const float* Bg = g_w1c + (size_t)e * D_ * H_ + n0;

    float acc[4][4][4];
    #pragma unroll
    for (int i = 0; i < 4; i++)
        #pragma unroll
        for (int j = 0; j < 4; j++)
            #pragma unroll
            for (int r = 0; r < 4; r++) acc[i][j][r] = 0.f;

    const int NK = D_ / BK;   // 16
    #define A1(r, c) (Ag + (size_t)(r) * D_ + (size_t)kk * BK + (c) * 4)
    #define B1(r, c) (Bg + (size_t)((size_t)kk * BK + (r)) * H_ + (c) * 4)

    // prologue: stages 0..STAGES-2
    #pragma unroll
    for (int s = 0; s < STAGES - 1; s++) {
        const int kk = s;
        ISSUE_STAGE(s, A1, B1);
        cp_commit();
    }

    for (int kt = 0; kt < NK; kt++) {
        cp_wait<STAGES - 2>();
        __syncthreads();
        const int pf = kt + STAGES - 1;
        if (pf < NK) {
            const int kk = pf;
            ISSUE_STAGE(pf % STAGES, A1, B1);
        }
        cp_commit();
        COMPUTE_STAGE(kt % STAGES);
    }
    #undef A1
    #undef B1

    // epilogue: +b1, silu, *p, rna, write
    const float* brow = b1 + (size_t)e * H_ + n0;
    float* Hb = g_h + ((size_t)b * T_ + m0) * (2 * H_) + (size_t)slot * H_ + n0;
    #pragma unroll
    for (int mt = 0; mt < 4; mt++) {
        #pragma unroll
        for (int nt = 0; nt < 4; nt++) {
            #pragma unroll
            for (int half = 0; half < 2; half++) {
                const int row = wm + mt * 16 + g + half * 8;
                const int col = wn + nt * 8 + t4 * 2;
                float v0 = acc[mt][nt][half * 2 + 0] + brow[col];
                float v1 = acc[mt][nt][half * 2 + 1] + brow[col + 1];
                v0 = rna32(p * v0 * (1.0f / (1.0f + __expf(-v0))));
                v1 = rna32(p * v1 * (1.0f / (1.0f + __expf(-v1))));
                *(float2*)&Hb[(size_t)row * (2 * H_) + col] = make_float2(v0, v1);
            }
        }
    }
}

// ---------------------------------------------------------------------------
// GEMM2: out[b] = h_cat[b] @ [w2c[e0]; w2c[e1]] + p0*b2[e0] + p1*b2[e1] + x[b]
// A: g_h[b]  [T, 2H] row-major; B: row kk -> w2c[e][kk mod H][*]  (k rows)
// grid (D/BN=4, T/BM=8, B=32)
// ---------------------------------------------------------------------------
__global__ __launch_bounds__(256, 2) void gemm2_kernel(const float* __restrict__ x,
                                                       const float* __restrict__ b2,
                                                       float* __restrict__ out) {
    extern __shared__ char smem[];
    const uint32_t sm_base = smem_u32(smem);

    const int b = blockIdx.z;
    const int e0 = g_eidx[b][0], e1 = g_eidx[b][1];
    const float p0 = g_prob[b][0], p1 = g_prob[b][1];
    const int m0 = blockIdx.y * BM;
    const int n0 = blockIdx.x * BN;
    const int tid  = threadIdx.x;
    const int warp = tid >> 5, lane = tid & 31;
    const int g = lane >> 2, t4 = lane & 3;
    const int wm = (warp & 1) * 64;
    const int wn = (warp >> 1) * 32;

    const float* Ag  = g_h + ((size_t)b * T_ + m0) * (2 * H_);
    const float* Bg0 = g_w2c + (size_t)e0 * H_ * D_ + n0;
    const float* Bg1 = g_w2c + (size_t)e1 * H_ * D_ + n0;

    float acc[4][4][4];
    #pragma unroll
    for (int i = 0; i < 4; i++)
        #pragma unroll
        for (int j = 0; j < 4; j++)
            #pragma unroll
            for (int r = 0; r < 4; r++) acc[i][j][r] = 0.f;

    const int NK = (2 * H_) / BK;   // 128
    #define A2(r, c) (Ag + (size_t)(r) * (2 * H_) + (size_t)kk * BK + (c) * 4)
    #define B2(r, c) ((kk < 64 ? Bg0 : Bg1) + \
                      (size_t)(((size_t)(kk & 63)) * BK + (r)) * D_ + (c) * 4)

    #pragma unroll
    for (int s = 0; s < STAGES - 1; s++) {
        const int kk = s;
        ISSUE_STAGE(s, A2, B2);
        cp_commit();
    }

    for (int kt = 0; kt < NK; kt++) {
        cp_wait<STAGES - 2>();
        __syncthreads();
        const int pf = kt + STAGES - 1;
        if (pf < NK) {
            const int kk = pf;
            ISSUE_STAGE(pf % STAGES, A2, B2);
        }
        cp_commit();
        COMPUTE_STAGE(kt % STAGES);
    }
    #undef A2
    #undef B2

    // epilogue: + p0*b2[e0] + p1*b2[e1] + x, write out
    const float* b2r0 = b2 + (size_t)e0 * D_ + n0;
    const float* b2r1 = b2 + (size_t)e1 * D_ + n0;
    const float* xb = x   + ((size_t)b * T_ + m0) * D_ + n0;
    float*       ob = out + ((size_t)b * T_ + m0) * D_ + n0;
    #pragma unroll
    for (int mt = 0; mt < 4; mt++) {
        #pragma unroll
        for (int nt = 0; nt < 4; nt++) {
            #pragma unroll
            for (int half = 0; half < 2; half++) {
                const int row = wm + mt * 16 + g + half * 8;
                const int col = wn + nt * 8 + t4 * 2;
                const float bias0 = p0 * b2r0[col]     + p1 * b2r1[col];
                const float bias1 = p0 * b2r0[col + 1] + p1 * b2r1[col + 1];
                const float2 xv = *(const float2*)&xb[(size_t)row * D_ + col];
                float v0 = acc[mt][nt][half * 2 + 0] + bias0 + xv.x;
                float v1 = acc[mt][nt][half * 2 + 1] + bias1 + xv.y;
                *(float2*)&ob[(size_t)row * D_ + col] = make_float2(v0, v1);
            }
        }
    }
}

// ---------------------------------------------------------------------------
extern "C" void kernel_launch(void* const* d_in, const int* in_sizes, int n_in,
                              void* d_out, int out_size) {
    const float* x  = (const float*)d_in[0];
    const float* gw = (const float*)d_in[1];
    const float* gb = (const float*)d_in[2];
    const float* w1 = (const float*)d_in[3];
    const float* b1 = (const float*)d_in[4];
    const float* w2 = (const float*)d_in[5];
    const float* b2 = (const float*)d_in[6];

    float* out = (float*)d_out;
    float* out_logits = out + (size_t)B_ * T_ * D_;

    static int configured = 0;
    cudaFuncSetAttribute(gemm1_kernel, cudaFuncAttributeMaxDynamicSharedMemorySize, SMEMSZ);
    cudaFuncSetAttribute(gemm2_kernel, cudaFuncAttributeMaxDynamicSharedMemorySize, SMEMSZ);
    (void)configured;

    // prep: pooling + RNA copies
    pool_convert_kernel<<<dim3(B_, 8), 512>>>(x);
    {
        float* w1c_ptr; cudaGetSymbolAddress((void**)&w1c_ptr, g_w1c);
        float* w2c_ptr; cudaGetSymbolAddress((void**)&w2c_ptr, g_w2c);
        const size_t n4 = (size_t)E_ * D_ * H_ / 4;   // 2M float4
        round_copy_kernel<<<(unsigned)((n4 + 255) / 256), 256>>>(w1, w1c_ptr, n4);
        round_copy_kernel<<<(unsigned)((n4 + 255) / 256), 256>>>(w2, w2c_ptr, n4);
    }
    gate_kernel<<<B_, 512>>>(gw, gb, out_logits);

    gemm1_kernel<<<dim3(H_ / BN, T_ / BM, B_ * 2), 256, SMEMSZ>>>(b1);
    gemm2_kernel<<<dim3(D_ / BN, T_ / BM, B_), 256, SMEMSZ>>>(x, b2, out);
}